// round 1
// baseline (speedup 1.0000x reference)
#include <cuda_runtime.h>
#include <math.h>

#define NB 32
#define NC 256
#define NH 64
#define NW 64
#define HW (NH*NW)          // 4096
#define HW4 (HW/4)          // 1024 float4 groups per (b,c) plane
#define KS 7
#define PAD 3

// scratch: per image, [max plane (4096 floats), mean plane (4096 floats)]
__device__ float g_stats[NB * 2 * HW];

// ---------------------------------------------------------------------------
// Kernel A: per-pixel channel max + mean.  One thread = 4 consecutive w pixels.
// 32768 threads total. Fully coalesced float4 loads, stride HW between channels.
// ---------------------------------------------------------------------------
__global__ void __launch_bounds__(128) reduce_kernel(const float* __restrict__ x)
{
    int idx = blockIdx.x * blockDim.x + threadIdx.x;   // 0 .. 32767
    int b = idx >> 10;          // image
    int g = idx & 1023;         // float4 group within image (= h*16 + w/4)

    const float4* xb = reinterpret_cast<const float4*>(x) + (size_t)b * NC * HW4 + g;

    float4 mx = make_float4(-INFINITY, -INFINITY, -INFINITY, -INFINITY);
    float4 sm = make_float4(0.f, 0.f, 0.f, 0.f);

    #pragma unroll 8
    for (int c = 0; c < NC; c++) {
        float4 v = __ldg(xb + c * HW4);
        mx.x = fmaxf(mx.x, v.x);  sm.x += v.x;
        mx.y = fmaxf(mx.y, v.y);  sm.y += v.y;
        mx.z = fmaxf(mx.z, v.z);  sm.z += v.z;
        mx.w = fmaxf(mx.w, v.w);  sm.w += v.w;
    }

    const float inv = 1.0f / (float)NC;
    float4 mean4 = make_float4(sm.x * inv, sm.y * inv, sm.z * inv, sm.w * inv);

    float4* smax  = reinterpret_cast<float4*>(g_stats + (size_t)b * 2 * HW);
    float4* smean = smax + HW4;
    smax[g]  = mx;
    smean[g] = mean4;
}

// ---------------------------------------------------------------------------
// Kernel B: 7x7 conv over [max, mean] stats -> sigmoid -> x * scale.
// One thread = 4 consecutive w pixels; 256 channel iterations of ld.128/st.128.
// Stats are 32 KB per image -> L1/L2 hot; weights staged in smem.
// ---------------------------------------------------------------------------
__global__ void __launch_bounds__(128) conv_scale_kernel(const float* __restrict__ x,
                                                         const float* __restrict__ wgt,
                                                         float* __restrict__ out)
{
    __shared__ float sw[2 * KS * KS];   // [ic=0: max weights][ic=1: mean weights]
    if (threadIdx.x < 2 * KS * KS) sw[threadIdx.x] = wgt[threadIdx.x];
    __syncthreads();

    int idx = blockIdx.x * blockDim.x + threadIdx.x;   // 0 .. 32767
    int b = idx >> 10;
    int g = idx & 1023;
    int h  = g >> 4;            // row (16 float4 groups per row)
    int w0 = (g & 15) << 2;     // first w of this thread's 4 pixels

    const float* smax  = g_stats + (size_t)b * 2 * HW;
    const float* smean = smax + HW;

    float acc0 = 0.f, acc1 = 0.f, acc2 = 0.f, acc3 = 0.f;

    #pragma unroll
    for (int kh = 0; kh < KS; kh++) {
        int ih = h + kh - PAD;
        if (ih < 0 || ih >= NH) continue;
        const float* rmax  = smax  + ih * NW;
        const float* rmean = smean + ih * NW;
        #pragma unroll
        for (int kw = 0; kw < KS; kw++) {
            float wm = sw[kh * KS + kw];
            float wa = sw[KS * KS + kh * KS + kw];
            int iw = w0 + kw - PAD;
            // pixel 0..3 share the weight; bounds-check each
            if (iw >= 0 && iw < NW)       { acc0 += __ldg(rmax + iw)     * wm + __ldg(rmean + iw)     * wa; }
            if (iw + 1 >= 0 && iw + 1 < NW) { acc1 += __ldg(rmax + iw + 1) * wm + __ldg(rmean + iw + 1) * wa; }
            if (iw + 2 >= 0 && iw + 2 < NW) { acc2 += __ldg(rmax + iw + 2) * wm + __ldg(rmean + iw + 2) * wa; }
            if (iw + 3 >= 0 && iw + 3 < NW) { acc3 += __ldg(rmax + iw + 3) * wm + __ldg(rmean + iw + 3) * wa; }
        }
    }

    float s0 = 1.0f / (1.0f + __expf(-acc0));
    float s1 = 1.0f / (1.0f + __expf(-acc1));
    float s2 = 1.0f / (1.0f + __expf(-acc2));
    float s3 = 1.0f / (1.0f + __expf(-acc3));

    const float4* xb = reinterpret_cast<const float4*>(x)   + (size_t)b * NC * HW4 + g;
    float4*       ob = reinterpret_cast<float4*>(out)       + (size_t)b * NC * HW4 + g;

    #pragma unroll 4
    for (int c = 0; c < NC; c++) {
        float4 v = __ldg(xb + c * HW4);
        v.x *= s0; v.y *= s1; v.z *= s2; v.w *= s3;
        ob[c * HW4] = v;
    }
}

extern "C" void kernel_launch(void* const* d_in, const int* in_sizes, int n_in,
                              void* d_out, int out_size)
{
    const float* x = (const float*)d_in[0];
    const float* w = (const float*)d_in[1];
    float* out = (float*)d_out;

    // 32768 threads covering B*H*W/4 float4 pixel groups
    dim3 block(128);
    dim3 grid((NB * HW4) / 128);   // 256 blocks

    reduce_kernel<<<grid, block>>>(x);
    conv_scale_kernel<<<grid, block>>>(x, w, out);
}

// round 2
// speedup vs baseline: 1.5196x; 1.5196x over previous
#include <cuda_runtime.h>
#include <math.h>

#define NB 32
#define NC 256
#define NH 64
#define NW 64
#define HW (NH*NW)          // 4096
#define HW4 (HW/4)          // 1024 float4 groups per (b,c) plane
#define KS 7
#define PAD 3

// scratch: per image, [max plane (4096 floats), mean plane (4096 floats)]
__device__ float g_stats[NB * 2 * HW];
// sigmoid(conv) result, one float per pixel
__device__ float g_scale[NB * HW];

// ---------------------------------------------------------------------------
// Kernel A: channel max + mean, channel dim split 8 ways for occupancy.
// Block = 256 threads = 32 pixel-groups (float4) x 8 channel-splits.
// Each thread loads 32 channels; smem combine. 1024 blocks.
// ---------------------------------------------------------------------------
__global__ void __launch_bounds__(256) reduce_kernel(const float* __restrict__ x)
{
    __shared__ float4 s_max[8][32];
    __shared__ float4 s_sum[8][32];

    int tid = threadIdx.x;
    int pix = tid & 31;           // pixel-group lane (warp-contiguous)
    int cs  = tid >> 5;           // channel split 0..7

    int gp = blockIdx.x * 32 + pix;   // global float4 group, 0..32767
    int b  = gp >> 10;
    int g  = gp & 1023;

    const float4* xb = reinterpret_cast<const float4*>(x)
                     + (size_t)b * NC * HW4 + (size_t)(cs * 32) * HW4 + g;

    float4 mx = make_float4(-INFINITY, -INFINITY, -INFINITY, -INFINITY);
    float4 sm = make_float4(0.f, 0.f, 0.f, 0.f);

    #pragma unroll 8
    for (int c = 0; c < 32; c++) {
        float4 v = __ldg(xb + c * HW4);
        mx.x = fmaxf(mx.x, v.x);  sm.x += v.x;
        mx.y = fmaxf(mx.y, v.y);  sm.y += v.y;
        mx.z = fmaxf(mx.z, v.z);  sm.z += v.z;
        mx.w = fmaxf(mx.w, v.w);  sm.w += v.w;
    }

    s_max[cs][pix] = mx;
    s_sum[cs][pix] = sm;
    __syncthreads();

    if (cs == 0) {
        #pragma unroll
        for (int k = 1; k < 8; k++) {
            float4 m = s_max[k][pix];
            float4 s = s_sum[k][pix];
            mx.x = fmaxf(mx.x, m.x);  sm.x += s.x;
            mx.y = fmaxf(mx.y, m.y);  sm.y += s.y;
            mx.z = fmaxf(mx.z, m.z);  sm.z += s.z;
            mx.w = fmaxf(mx.w, m.w);  sm.w += s.w;
        }
        const float inv = 1.0f / (float)NC;
        float4 mean4 = make_float4(sm.x * inv, sm.y * inv, sm.z * inv, sm.w * inv);

        float4* smax  = reinterpret_cast<float4*>(g_stats + (size_t)b * 2 * HW);
        float4* smean = smax + HW4;
        smax[g]  = mx;
        smean[g] = mean4;
    }
}

// ---------------------------------------------------------------------------
// Kernel B: 7x7 conv over [max, mean] stats -> sigmoid -> g_scale.
// Tiny: 32768 threads, stats are L2-hot. One thread = 4 pixels.
// ---------------------------------------------------------------------------
__global__ void __launch_bounds__(128) conv_kernel(const float* __restrict__ wgt)
{
    __shared__ float sw[2 * KS * KS];
    if (threadIdx.x < 2 * KS * KS) sw[threadIdx.x] = wgt[threadIdx.x];
    __syncthreads();

    int idx = blockIdx.x * blockDim.x + threadIdx.x;   // 0 .. 32767
    int b = idx >> 10;
    int g = idx & 1023;
    int h  = g >> 4;
    int w0 = (g & 15) << 2;

    const float* smax  = g_stats + (size_t)b * 2 * HW;
    const float* smean = smax + HW;

    float acc0 = 0.f, acc1 = 0.f, acc2 = 0.f, acc3 = 0.f;

    #pragma unroll
    for (int kh = 0; kh < KS; kh++) {
        int ih = h + kh - PAD;
        if (ih < 0 || ih >= NH) continue;
        const float* rmax  = smax  + ih * NW;
        const float* rmean = smean + ih * NW;
        #pragma unroll
        for (int kw = 0; kw < KS; kw++) {
            float wm = sw[kh * KS + kw];
            float wa = sw[KS * KS + kh * KS + kw];
            int iw = w0 + kw - PAD;
            if (iw >= 0 && iw < NW)         { acc0 += __ldg(rmax + iw)     * wm + __ldg(rmean + iw)     * wa; }
            if (iw + 1 >= 0 && iw + 1 < NW) { acc1 += __ldg(rmax + iw + 1) * wm + __ldg(rmean + iw + 1) * wa; }
            if (iw + 2 >= 0 && iw + 2 < NW) { acc2 += __ldg(rmax + iw + 2) * wm + __ldg(rmean + iw + 2) * wa; }
            if (iw + 3 >= 0 && iw + 3 < NW) { acc3 += __ldg(rmax + iw + 3) * wm + __ldg(rmean + iw + 3) * wa; }
        }
    }

    float4 s;
    s.x = 1.0f / (1.0f + __expf(-acc0));
    s.y = 1.0f / (1.0f + __expf(-acc1));
    s.z = 1.0f / (1.0f + __expf(-acc2));
    s.w = 1.0f / (1.0f + __expf(-acc3));

    reinterpret_cast<float4*>(g_scale)[(size_t)b * HW4 + g] = s;
}

// ---------------------------------------------------------------------------
// Kernel C: out = x * scale. Pure streaming. 1M threads, 8 channels/thread.
// idx bits: [b:5][cs:5][g:10]
// ---------------------------------------------------------------------------
#define CPT 8
__global__ void __launch_bounds__(256) scale_kernel(const float* __restrict__ x,
                                                    float* __restrict__ out)
{
    int idx = blockIdx.x * blockDim.x + threadIdx.x;
    int g  = idx & 1023;
    int cs = (idx >> 10) & 31;
    int b  = idx >> 15;

    float4 s = __ldg(reinterpret_cast<const float4*>(g_scale) + (size_t)b * HW4 + g);

    const float4* xb = reinterpret_cast<const float4*>(x)
                     + ((size_t)b * NC + cs * CPT) * HW4 + g;
    float4* ob = reinterpret_cast<float4*>(out)
                     + ((size_t)b * NC + cs * CPT) * HW4 + g;

    #pragma unroll
    for (int c = 0; c < CPT; c++) {
        float4 v = __ldg(xb + c * HW4);
        v.x *= s.x; v.y *= s.y; v.z *= s.z; v.w *= s.w;
        ob[c * HW4] = v;
    }
}

extern "C" void kernel_launch(void* const* d_in, const int* in_sizes, int n_in,
                              void* d_out, int out_size)
{
    const float* x = (const float*)d_in[0];
    const float* w = (const float*)d_in[1];
    float* out = (float*)d_out;

    reduce_kernel<<<1024, 256>>>(x);                    // 32 pix-groups x 8 splits per block
    conv_kernel<<<256, 128>>>(w);                       // 32768 threads
    scale_kernel<<<(NB * 32 * HW4) / 256, 256>>>(x, out); // 4096 blocks
}

// round 3
// speedup vs baseline: 1.6113x; 1.0604x over previous
#include <cuda_runtime.h>
#include <math.h>

#define NB 32
#define NC 256
#define NH 64
#define NW 64
#define HW (NH*NW)          // 4096
#define HW4 (HW/4)          // 1024 float4 groups per (b,c) plane
#define KS 7
#define PAD 3

__device__ float g_stats[NB * 2 * HW];   // per image: [max plane][mean plane]
__device__ float g_scale[NB * HW];       // sigmoid(conv)

// ---------------------------------------------------------------------------
// Kernel A: channel max+mean, 16-way channel split.
// Block = 512 threads = 32 pixel-groups (float4) x 16 channel-splits.
// Each thread loads 16 channels (float4); smem combine. 1024 blocks.
// ---------------------------------------------------------------------------
__global__ void __launch_bounds__(512) reduce_kernel(const float* __restrict__ x)
{
    __shared__ float4 s_max[16][32];
    __shared__ float4 s_sum[16][32];

    int tid = threadIdx.x;
    int pix = tid & 31;           // pixel-group lane (warp-contiguous)
    int cs  = tid >> 5;           // channel split 0..15

    int gp = blockIdx.x * 32 + pix;   // global float4 group, 0..32767
    int b  = gp >> 10;
    int g  = gp & 1023;

    const float4* xb = reinterpret_cast<const float4*>(x)
                     + (size_t)b * NC * HW4 + (size_t)(cs * 16) * HW4 + g;

    float4 mx = make_float4(-INFINITY, -INFINITY, -INFINITY, -INFINITY);
    float4 sm = make_float4(0.f, 0.f, 0.f, 0.f);

    #pragma unroll
    for (int c = 0; c < 16; c++) {
        float4 v = __ldg(xb + c * HW4);
        mx.x = fmaxf(mx.x, v.x);  sm.x += v.x;
        mx.y = fmaxf(mx.y, v.y);  sm.y += v.y;
        mx.z = fmaxf(mx.z, v.z);  sm.z += v.z;
        mx.w = fmaxf(mx.w, v.w);  sm.w += v.w;
    }

    s_max[cs][pix] = mx;
    s_sum[cs][pix] = sm;
    __syncthreads();

    if (cs == 0) {
        #pragma unroll
        for (int k = 1; k < 16; k++) {
            float4 m = s_max[k][pix];
            float4 s = s_sum[k][pix];
            mx.x = fmaxf(mx.x, m.x);  sm.x += s.x;
            mx.y = fmaxf(mx.y, m.y);  sm.y += s.y;
            mx.z = fmaxf(mx.z, m.z);  sm.z += s.z;
            mx.w = fmaxf(mx.w, m.w);  sm.w += s.w;
        }
        const float inv = 1.0f / (float)NC;
        float4 mean4 = make_float4(sm.x * inv, sm.y * inv, sm.z * inv, sm.w * inv);

        float4* smax  = reinterpret_cast<float4*>(g_stats + (size_t)b * 2 * HW);
        float4* smean = smax + HW4;
        smax[g]  = mx;
        smean[g] = mean4;
    }
}

// ---------------------------------------------------------------------------
// Kernel B: 7x7 conv over [max, mean] stats -> sigmoid -> g_scale.
// ---------------------------------------------------------------------------
__global__ void __launch_bounds__(128) conv_kernel(const float* __restrict__ wgt)
{
    __shared__ float sw[2 * KS * KS];
    if (threadIdx.x < 2 * KS * KS) sw[threadIdx.x] = wgt[threadIdx.x];
    __syncthreads();

    int idx = blockIdx.x * blockDim.x + threadIdx.x;   // 0 .. 32767
    int b = idx >> 10;
    int g = idx & 1023;
    int h  = g >> 4;
    int w0 = (g & 15) << 2;

    const float* smax  = g_stats + (size_t)b * 2 * HW;
    const float* smean = smax + HW;

    float acc0 = 0.f, acc1 = 0.f, acc2 = 0.f, acc3 = 0.f;

    #pragma unroll
    for (int kh = 0; kh < KS; kh++) {
        int ih = h + kh - PAD;
        if (ih < 0 || ih >= NH) continue;
        const float* rmax  = smax  + ih * NW;
        const float* rmean = smean + ih * NW;
        #pragma unroll
        for (int kw = 0; kw < KS; kw++) {
            float wm = sw[kh * KS + kw];
            float wa = sw[KS * KS + kh * KS + kw];
            int iw = w0 + kw - PAD;
            if (iw >= 0 && iw < NW)         { acc0 += __ldg(rmax + iw)     * wm + __ldg(rmean + iw)     * wa; }
            if (iw + 1 >= 0 && iw + 1 < NW) { acc1 += __ldg(rmax + iw + 1) * wm + __ldg(rmean + iw + 1) * wa; }
            if (iw + 2 >= 0 && iw + 2 < NW) { acc2 += __ldg(rmax + iw + 2) * wm + __ldg(rmean + iw + 2) * wa; }
            if (iw + 3 >= 0 && iw + 3 < NW) { acc3 += __ldg(rmax + iw + 3) * wm + __ldg(rmean + iw + 3) * wa; }
        }
    }

    float4 s;
    s.x = 1.0f / (1.0f + __expf(-acc0));
    s.y = 1.0f / (1.0f + __expf(-acc1));
    s.z = 1.0f / (1.0f + __expf(-acc2));
    s.w = 1.0f / (1.0f + __expf(-acc3));

    reinterpret_cast<float4*>(g_scale)[(size_t)b * HW4 + g] = s;
}

// ---------------------------------------------------------------------------
// Kernel C: out = x * scale. REVERSED block order: consume the L2-hot tail
// of x (just read by reduce_kernel) first. x loads use .cs (last use),
// out stores use .cs (streaming) to minimize L2 pollution.
// idx bits: [b:5][cs:5][g:10]
// ---------------------------------------------------------------------------
#define CPT 8
__global__ void __launch_bounds__(256) scale_kernel(const float* __restrict__ x,
                                                    float* __restrict__ out)
{
    // reverse at block granularity so later addresses (L2-hot) go first
    int rbid = gridDim.x - 1 - blockIdx.x;
    int idx = rbid * blockDim.x + threadIdx.x;
    int g  = idx & 1023;
    int cs = (idx >> 10) & 31;
    int b  = idx >> 15;

    float4 s = __ldg(reinterpret_cast<const float4*>(g_scale) + (size_t)b * HW4 + g);

    const float4* xb = reinterpret_cast<const float4*>(x)
                     + ((size_t)b * NC + cs * CPT) * HW4 + g;
    float4* ob = reinterpret_cast<float4*>(out)
                     + ((size_t)b * NC + cs * CPT) * HW4 + g;

    #pragma unroll
    for (int c = 0; c < CPT; c++) {
        float4 v = __ldcs(xb + c * HW4);   // last use of x: evict-first
        v.x *= s.x; v.y *= s.y; v.z *= s.z; v.w *= s.w;
        __stcs(ob + c * HW4, v);           // streaming store
    }
}

extern "C" void kernel_launch(void* const* d_in, const int* in_sizes, int n_in,
                              void* d_out, int out_size)
{
    const float* x = (const float*)d_in[0];
    const float* w = (const float*)d_in[1];
    float* out = (float*)d_out;

    reduce_kernel<<<1024, 512>>>(x);                      // 32 pix-groups x 16 splits
    conv_kernel<<<256, 128>>>(w);                         // 32768 threads
    scale_kernel<<<(NB * 32 * HW4) / 256, 256>>>(x, out); // 4096 blocks
}